// round 1
// baseline (speedup 1.0000x reference)
#include <cuda_runtime.h>
#include <cuda_bf16.h>
#include <math.h>

// Problem constants
#define B_    2
#define CIN   64
#define COUT  64
#define DIN   64
#define DOUT  62
#define KTAPS 27
#define EPS_  1e-8f

// Scratch for modulated/demodulated weights, layout [b][cin][tap][cout]
__device__ float g_wn[B_ * CIN * KTAPS * COUT];
__device__ float g_dw[B_ * CIN * KTAPS * COUT];

// ---------------------------------------------------------------------------
// Prep kernel: one block per (b, cout). Computes
//   smod[b,ci]  = s[b,:] . style_weight[ci,:] + style_bias[ci]
//   dsmod[b,ci] = style_weight[ci,1]                (ds = e_1)
//   w  = weight * smod ; dws = weight * dsmod
//   norm = sqrt(sum w^2 + EPS); dnorm = -sum(w*dws)/norm^3
//   wn = w/norm ; dw = dws/norm + w*dnorm
// ---------------------------------------------------------------------------
__global__ void prep_kernel(const float* __restrict__ s,
                            const float* __restrict__ style_weight,
                            const float* __restrict__ style_bias,
                            const float* __restrict__ weight)
{
    __shared__ float wsm[CIN * KTAPS];
    __shared__ float dwsm[CIN * KTAPS];
    __shared__ float red0[256];
    __shared__ float red1[256];

    const int b  = blockIdx.x >> 6;
    const int co = blockIdx.x & 63;
    const int tid = threadIdx.x;

    const float s0 = s[b * 2 + 0];
    const float s1 = s[b * 2 + 1];

    float sw2 = 0.f, swd = 0.f;
    for (int e = tid; e < CIN * KTAPS; e += 256) {
        const int ci = e / KTAPS;
        const int t  = e - ci * KTAPS;
        const float smod  = s0 * style_weight[ci * 2 + 0]
                          + s1 * style_weight[ci * 2 + 1]
                          + style_bias[ci];
        const float dsmod = style_weight[ci * 2 + 1];
        const float wt = weight[(co * CIN + ci) * KTAPS + t];
        const float wv = wt * smod;
        const float dv = wt * dsmod;
        wsm[e]  = wv;
        dwsm[e] = dv;
        sw2 += wv * wv;
        swd += wv * dv;
    }
    red0[tid] = sw2;
    red1[tid] = swd;
    __syncthreads();
    for (int st = 128; st > 0; st >>= 1) {
        if (tid < st) {
            red0[tid] += red0[tid + st];
            red1[tid] += red1[tid + st];
        }
        __syncthreads();
    }
    const float norm  = sqrtf(red0[0] + EPS_);
    const float inv   = 1.0f / norm;
    const float dnorm = -red1[0] * inv * inv * inv;

    for (int e = tid; e < CIN * KTAPS; e += 256) {
        const int ci = e / KTAPS;
        const int t  = e - ci * KTAPS;
        const size_t oidx = ((size_t)((b * CIN + ci) * KTAPS + t)) * COUT + co;
        g_wn[oidx] = wsm[e] * inv;
        g_dw[oidx] = dwsm[e] * inv + wsm[e] * dnorm;
    }
}

// ---------------------------------------------------------------------------
// Fused conv kernel: computes both
//   y  = x  (*) wn + bias
//   dy = x  (*) dw + dx (*) wn
// Block tile: all 64 couts x (2 output rows x 64 x-positions) at fixed (b,z).
// Thread: mi=8 couts x ni=4 positions (2 rows x {tx, tx+32}).
// Per tap per thread: 12 LDS-instr, 96 FFMA  -> FFMA-issue bound.
// ---------------------------------------------------------------------------
__global__ __launch_bounds__(256, 2) void conv_kernel(
    const float* __restrict__ x,
    const float* __restrict__ dx,
    const float* __restrict__ bias,
    float* __restrict__ out)
{
    __shared__ __align__(16) float xs [3][4][68];   // 3 z-planes, 4 rows, 66 used cols
    __shared__ __align__(16) float dxs[3][4][68];
    __shared__ __align__(16) float ws [KTAPS][COUT];
    __shared__ __align__(16) float dws[KTAPS][COUT];

    const int z     = blockIdx.x;       // 0..61
    const int ytile = blockIdx.y;       // 0..30
    const int b     = blockIdx.z;       // 0..1
    const int y0    = ytile * 2;

    const int tid = threadIdx.x;
    const int tc  = tid >> 5;           // cout group 0..7
    const int tx  = tid & 31;           // x lane

    float accy[8][4] = {};
    float accd[8][4] = {};

    const size_t chan_sz = (size_t)DIN * DIN * DIN;            // 262144
    const float* xb  = x  + (size_t)b * CIN * chan_sz;
    const float* dxb = dx + (size_t)b * CIN * chan_sz;
    const float* wb  = g_wn + (size_t)b * CIN * KTAPS * COUT;
    const float* dwb = g_dw + (size_t)b * CIN * KTAPS * COUT;

    for (int ci = 0; ci < CIN; ci++) {
        __syncthreads();
        // ---- stage input patch (3 x 4 x 66) for x and dx ----
        {
            const size_t base = (size_t)ci * chan_sz + (size_t)z * (DIN * DIN) + (size_t)y0 * DIN;
            const float* xc  = xb  + base;
            const float* dxc = dxb + base;
            for (int i = tid; i < 3 * 4 * 66; i += 256) {
                const int dz  = i / 264;
                const int rem = i - dz * 264;
                const int row = rem / 66;
                const int col = rem - row * 66;
                float v = 0.f, dv = 0.f;
                if (col < DIN) {
                    const size_t off = (size_t)dz * (DIN * DIN) + row * DIN + col;
                    v  = xc[off];
                    dv = dxc[off];
                }
                xs [dz][row][col] = v;
                dxs[dz][row][col] = dv;
            }
        }
        // ---- stage weights for this cin: 27x64 floats each ----
        {
            const float4* wsrc  = (const float4*)(wb  + (size_t)ci * KTAPS * COUT);
            const float4* dwsrc = (const float4*)(dwb + (size_t)ci * KTAPS * COUT);
            float4* wdst  = (float4*)&ws[0][0];
            float4* dwdst = (float4*)&dws[0][0];
            for (int i = tid; i < KTAPS * (COUT / 4); i += 256) {
                wdst[i]  = wsrc[i];
                dwdst[i] = dwsrc[i];
            }
        }
        __syncthreads();

        // ---- compute: 27 taps ----
        #pragma unroll 1
        for (int dz = 0; dz < 3; dz++) {
            #pragma unroll
            for (int r = 0; r < 3; r++) {
                #pragma unroll
                for (int c = 0; c < 3; c++) {
                    const int t = (dz * 3 + r) * 3 + c;
                    const float4 w0 = *(const float4*)&ws [t][tc * 8];
                    const float4 w1 = *(const float4*)&ws [t][tc * 8 + 4];
                    const float4 d0 = *(const float4*)&dws[t][tc * 8];
                    const float4 d1 = *(const float4*)&dws[t][tc * 8 + 4];
                    const float wr[8] = {w0.x, w0.y, w0.z, w0.w, w1.x, w1.y, w1.z, w1.w};
                    const float dr[8] = {d0.x, d0.y, d0.z, d0.w, d1.x, d1.y, d1.z, d1.w};

                    float xv[4], dxv[4];
                    #pragma unroll
                    for (int yy = 0; yy < 2; yy++) {
                        #pragma unroll
                        for (int h = 0; h < 2; h++) {
                            const int n = yy * 2 + h;
                            xv [n] = xs [dz][yy + r][tx + 32 * h + c];
                            dxv[n] = dxs[dz][yy + r][tx + 32 * h + c];
                        }
                    }
                    #pragma unroll
                    for (int m = 0; m < 8; m++) {
                        #pragma unroll
                        for (int n = 0; n < 4; n++) {
                            accy[m][n] = fmaf(xv[n],  wr[m], accy[m][n]);
                            accd[m][n] = fmaf(xv[n],  dr[m], accd[m][n]);
                            accd[m][n] = fmaf(dxv[n], wr[m], accd[m][n]);
                        }
                    }
                }
            }
        }
    }

    // ---- epilogue: write y then dy (concatenated output) ----
    const size_t NOUT   = (size_t)DOUT * DOUT * DOUT;          // 238328
    const size_t dy_off = (size_t)B_ * COUT * NOUT;            // start of dy

    #pragma unroll
    for (int m = 0; m < 8; m++) {
        const int co = tc * 8 + m;
        const float bv = bias[co];
        const size_t base_zy = ((size_t)(b * COUT + co) * DOUT + z) * DOUT;
        #pragma unroll
        for (int n = 0; n < 4; n++) {
            const int yy = n >> 1;
            const int h  = n & 1;
            const int xx = tx + 32 * h;
            if (xx < DOUT) {
                const size_t idx = (base_zy + (y0 + yy)) * DOUT + xx;
                out[idx]          = accy[m][n] + bv;
                out[dy_off + idx] = accd[m][n];
            }
        }
    }
}

// ---------------------------------------------------------------------------
// Launch
// Inputs (metadata order): x, s, dx, style_weight, style_bias, weight, bias
// Output: concat(y, dy) as float32, each (2,64,62,62,62)
// ---------------------------------------------------------------------------
extern "C" void kernel_launch(void* const* d_in, const int* in_sizes, int n_in,
                              void* d_out, int out_size)
{
    const float* x    = (const float*)d_in[0];
    const float* s    = (const float*)d_in[1];
    const float* dx   = (const float*)d_in[2];
    const float* sw   = (const float*)d_in[3];
    const float* sb   = (const float*)d_in[4];
    const float* w    = (const float*)d_in[5];
    const float* bias = (const float*)d_in[6];
    float* out = (float*)d_out;

    prep_kernel<<<B_ * COUT, 256>>>(s, sw, sb, w);

    dim3 grid(DOUT, (DOUT + 1) / 2, B_);   // (62, 31, 2)
    conv_kernel<<<grid, 256>>>(x, dx, bias, out);
}

// round 2
// speedup vs baseline: 1.0015x; 1.0015x over previous
#include <cuda_runtime.h>
#include <cuda_bf16.h>
#include <math.h>

// Problem constants
#define B_    2
#define CIN   64
#define COUT  64
#define DIN   64
#define DOUT  62
#define KTAPS 27
#define EPS_  1e-8f

// Scratch for modulated/demodulated weights, layout [b][cin][tap][cout]
__device__ float g_wn[B_ * CIN * KTAPS * COUT];
__device__ float g_dw[B_ * CIN * KTAPS * COUT];

// ---------------------------------------------------------------------------
// Prep kernel: one block per (b, cout). Computes
//   smod[b,ci]  = s[b,:] . style_weight[ci,:] + style_bias[ci]
//   dsmod[b,ci] = style_weight[ci,1]                (ds = e_1)
//   w  = weight * smod ; dws = weight * dsmod
//   norm = sqrt(sum w^2 + EPS); dnorm = -sum(w*dws)/norm^3
//   wn = w/norm ; dw = dws/norm + w*dnorm
// ---------------------------------------------------------------------------
__global__ void prep_kernel(const float* __restrict__ s,
                            const float* __restrict__ style_weight,
                            const float* __restrict__ style_bias,
                            const float* __restrict__ weight)
{
    __shared__ float wsm[CIN * KTAPS];
    __shared__ float dwsm[CIN * KTAPS];
    __shared__ float red0[256];
    __shared__ float red1[256];

    const int b  = blockIdx.x >> 6;
    const int co = blockIdx.x & 63;
    const int tid = threadIdx.x;

    const float s0 = s[b * 2 + 0];
    const float s1 = s[b * 2 + 1];

    float sw2 = 0.f, swd = 0.f;
    for (int e = tid; e < CIN * KTAPS; e += 256) {
        const int ci = e / KTAPS;
        const int t  = e - ci * KTAPS;
        const float smod  = s0 * style_weight[ci * 2 + 0]
                          + s1 * style_weight[ci * 2 + 1]
                          + style_bias[ci];
        const float dsmod = style_weight[ci * 2 + 1];
        const float wt = weight[(co * CIN + ci) * KTAPS + t];
        const float wv = wt * smod;
        const float dv = wt * dsmod;
        wsm[e]  = wv;
        dwsm[e] = dv;
        sw2 += wv * wv;
        swd += wv * dv;
    }
    red0[tid] = sw2;
    red1[tid] = swd;
    __syncthreads();
    for (int st = 128; st > 0; st >>= 1) {
        if (tid < st) {
            red0[tid] += red0[tid + st];
            red1[tid] += red1[tid + st];
        }
        __syncthreads();
    }
    const float norm  = sqrtf(red0[0] + EPS_);
    const float inv   = 1.0f / norm;
    const float dnorm = -red1[0] * inv * inv * inv;

    for (int e = tid; e < CIN * KTAPS; e += 256) {
        const int ci = e / KTAPS;
        const int t  = e - ci * KTAPS;
        const size_t oidx = ((size_t)((b * CIN + ci) * KTAPS + t)) * COUT + co;
        g_wn[oidx] = wsm[e] * inv;
        g_dw[oidx] = dwsm[e] * inv + wsm[e] * dnorm;
    }
}

// ---------------------------------------------------------------------------
// Fused conv kernel: computes both
//   y  = x  (*) wn + bias
//   dy = x  (*) dw + dx (*) wn
// Block tile: all 64 couts x (2 output rows x 64 x-positions) at fixed (b,z).
// Thread: mi=8 couts x ni=4 positions (2 rows x {tx, tx+32}).
// Per tap per thread: 12 LDS-instr, 96 FFMA  -> FFMA-issue bound.
// ---------------------------------------------------------------------------
__global__ __launch_bounds__(256, 2) void conv_kernel(
    const float* __restrict__ x,
    const float* __restrict__ dx,
    const float* __restrict__ bias,
    float* __restrict__ out)
{
    __shared__ __align__(16) float xs [3][4][68];   // 3 z-planes, 4 rows, 66 used cols
    __shared__ __align__(16) float dxs[3][4][68];
    __shared__ __align__(16) float ws [KTAPS][COUT];
    __shared__ __align__(16) float dws[KTAPS][COUT];

    const int z     = blockIdx.x;       // 0..61
    const int ytile = blockIdx.y;       // 0..30
    const int b     = blockIdx.z;       // 0..1
    const int y0    = ytile * 2;

    const int tid = threadIdx.x;
    const int tc  = tid >> 5;           // cout group 0..7
    const int tx  = tid & 31;           // x lane

    float accy[8][4] = {};
    float accd[8][4] = {};

    const size_t chan_sz = (size_t)DIN * DIN * DIN;            // 262144
    const float* xb  = x  + (size_t)b * CIN * chan_sz;
    const float* dxb = dx + (size_t)b * CIN * chan_sz;
    const float* wb  = g_wn + (size_t)b * CIN * KTAPS * COUT;
    const float* dwb = g_dw + (size_t)b * CIN * KTAPS * COUT;

    for (int ci = 0; ci < CIN; ci++) {
        __syncthreads();
        // ---- stage input patch (3 x 4 x 66) for x and dx ----
        {
            const size_t base = (size_t)ci * chan_sz + (size_t)z * (DIN * DIN) + (size_t)y0 * DIN;
            const float* xc  = xb  + base;
            const float* dxc = dxb + base;
            for (int i = tid; i < 3 * 4 * 66; i += 256) {
                const int dz  = i / 264;
                const int rem = i - dz * 264;
                const int row = rem / 66;
                const int col = rem - row * 66;
                float v = 0.f, dv = 0.f;
                if (col < DIN) {
                    const size_t off = (size_t)dz * (DIN * DIN) + row * DIN + col;
                    v  = xc[off];
                    dv = dxc[off];
                }
                xs [dz][row][col] = v;
                dxs[dz][row][col] = dv;
            }
        }
        // ---- stage weights for this cin: 27x64 floats each ----
        {
            const float4* wsrc  = (const float4*)(wb  + (size_t)ci * KTAPS * COUT);
            const float4* dwsrc = (const float4*)(dwb + (size_t)ci * KTAPS * COUT);
            float4* wdst  = (float4*)&ws[0][0];
            float4* dwdst = (float4*)&dws[0][0];
            for (int i = tid; i < KTAPS * (COUT / 4); i += 256) {
                wdst[i]  = wsrc[i];
                dwdst[i] = dwsrc[i];
            }
        }
        __syncthreads();

        // ---- compute: 27 taps ----
        #pragma unroll 1
        for (int dz = 0; dz < 3; dz++) {
            #pragma unroll
            for (int r = 0; r < 3; r++) {
                #pragma unroll
                for (int c = 0; c < 3; c++) {
                    const int t = (dz * 3 + r) * 3 + c;
                    const float4 w0 = *(const float4*)&ws [t][tc * 8];
                    const float4 w1 = *(const float4*)&ws [t][tc * 8 + 4];
                    const float4 d0 = *(const float4*)&dws[t][tc * 8];
                    const float4 d1 = *(const float4*)&dws[t][tc * 8 + 4];
                    const float wr[8] = {w0.x, w0.y, w0.z, w0.w, w1.x, w1.y, w1.z, w1.w};
                    const float dr[8] = {d0.x, d0.y, d0.z, d0.w, d1.x, d1.y, d1.z, d1.w};

                    float xv[4], dxv[4];
                    #pragma unroll
                    for (int yy = 0; yy < 2; yy++) {
                        #pragma unroll
                        for (int h = 0; h < 2; h++) {
                            const int n = yy * 2 + h;
                            xv [n] = xs [dz][yy + r][tx + 32 * h + c];
                            dxv[n] = dxs[dz][yy + r][tx + 32 * h + c];
                        }
                    }
                    #pragma unroll
                    for (int m = 0; m < 8; m++) {
                        #pragma unroll
                        for (int n = 0; n < 4; n++) {
                            accy[m][n] = fmaf(xv[n],  wr[m], accy[m][n]);
                            accd[m][n] = fmaf(xv[n],  dr[m], accd[m][n]);
                            accd[m][n] = fmaf(dxv[n], wr[m], accd[m][n]);
                        }
                    }
                }
            }
        }
    }

    // ---- epilogue: write y then dy (concatenated output) ----
    const size_t NOUT   = (size_t)DOUT * DOUT * DOUT;          // 238328
    const size_t dy_off = (size_t)B_ * COUT * NOUT;            // start of dy

    #pragma unroll
    for (int m = 0; m < 8; m++) {
        const int co = tc * 8 + m;
        const float bv = bias[co];
        const size_t base_zy = ((size_t)(b * COUT + co) * DOUT + z) * DOUT;
        #pragma unroll
        for (int n = 0; n < 4; n++) {
            const int yy = n >> 1;
            const int h  = n & 1;
            const int xx = tx + 32 * h;
            if (xx < DOUT) {
                const size_t idx = (base_zy + (y0 + yy)) * DOUT + xx;
                out[idx]          = accy[m][n] + bv;
                out[dy_off + idx] = accd[m][n];
            }
        }
    }
}

// ---------------------------------------------------------------------------
// Launch
// Inputs (metadata order): x, s, dx, style_weight, style_bias, weight, bias
// Output: concat(y, dy) as float32, each (2,64,62,62,62)
// ---------------------------------------------------------------------------
extern "C" void kernel_launch(void* const* d_in, const int* in_sizes, int n_in,
                              void* d_out, int out_size)
{
    const float* x    = (const float*)d_in[0];
    const float* s    = (const float*)d_in[1];
    const float* dx   = (const float*)d_in[2];
    const float* sw   = (const float*)d_in[3];
    const float* sb   = (const float*)d_in[4];
    const float* w    = (const float*)d_in[5];
    const float* bias = (const float*)d_in[6];
    float* out = (float*)d_out;

    prep_kernel<<<B_ * COUT, 256>>>(s, sw, sb, w);

    dim3 grid(DOUT, (DOUT + 1) / 2, B_);   // (62, 31, 2)
    conv_kernel<<<grid, 256>>>(x, dx, bias, out);
}

// round 4
// speedup vs baseline: 3.0618x; 3.0572x over previous
#include <cuda_runtime.h>
#include <cstdint>
#include <math.h>

// ---------------- problem constants ----------------
#define B_    2
#define CIN   64
#define COUT  64
#define DIN   64
#define DOUT  62
#define KTAPS 27
#define EPS_  1e-8f

#define NCHUNK 54                 // 27 taps x {x, dx}
#define ST_A   136                // floats per A smem row (k-major), 128 + 8 pad
#define ST_B   68                 // floats per B smem row (n-major), 64 + 4 pad
#define A_BYTES (64 * ST_A * 4)   // 34816
#define B_BYTES (256 * ST_B * 4)  // 69632
#define STAGE   (A_BYTES + B_BYTES)  // 104448
#define SMEM_DYN (2 * STAGE)         // 208896

// ---------------- device scratch ----------------
__device__ float g_wnv[B_ * COUT * CIN * KTAPS];
__device__ float g_dwv[B_ * COUT * CIN * KTAPS];
// A tiles: [b][kind][tap] x (64 k x 128 m) fp32(tf32-rounded), m contiguous
__device__ __align__(16) float g_A[B_ * 2 * KTAPS * 64 * 128];
// channel-last inputs [b][z][y][x][c], tf32-rounded, + pad for tap overreads
__device__ __align__(16) float g_xT [B_ * DIN * DIN * DIN * CIN + 16384];
__device__ __align__(16) float g_dxT[B_ * DIN * DIN * DIN * CIN + 16384];

// ---------------- helpers ----------------
__device__ __forceinline__ uint32_t smem_u32(const void* p) {
    uint32_t a;
    asm("{ .reg .u64 t; cvta.to.shared.u64 t, %1; cvt.u32.u64 %0, t; }" : "=r"(a) : "l"(p));
    return a;
}
__device__ __forceinline__ void cp_async16(uint32_t dst, const void* src) {
    asm volatile("cp.async.cg.shared.global [%0], [%1], 16;" :: "r"(dst), "l"(src) : "memory");
}
__device__ __forceinline__ uint32_t to_tf32(float v) {
    uint32_t u; asm("cvt.rna.tf32.f32 %0, %1;" : "=r"(u) : "f"(v)); return u;
}
__device__ __forceinline__ void mma_tf32(float* d, const uint32_t* a, const uint32_t* bfrag) {
    asm volatile(
        "mma.sync.aligned.m16n8k8.row.col.f32.tf32.tf32.f32 "
        "{%0,%1,%2,%3}, {%4,%5,%6,%7}, {%8,%9}, {%0,%1,%2,%3};"
        : "+f"(d[0]), "+f"(d[1]), "+f"(d[2]), "+f"(d[3])
        : "r"(a[0]), "r"(a[1]), "r"(a[2]), "r"(a[3]), "r"(bfrag[0]), "r"(bfrag[1]));
}

// ---------------------------------------------------------------------------
// Prep: style modulation + demodulation (validated in round 2)
// output layout [b][co][ci*27+t]
// ---------------------------------------------------------------------------
__global__ void prep_kernel(const float* __restrict__ s,
                            const float* __restrict__ style_weight,
                            const float* __restrict__ style_bias,
                            const float* __restrict__ weight)
{
    __shared__ float wsm[CIN * KTAPS];
    __shared__ float dwsm[CIN * KTAPS];
    __shared__ float red0[256];
    __shared__ float red1[256];

    const int b  = blockIdx.x >> 6;
    const int co = blockIdx.x & 63;
    const int tid = threadIdx.x;

    const float s0 = s[b * 2 + 0];
    const float s1 = s[b * 2 + 1];

    float sw2 = 0.f, swd = 0.f;
    for (int e = tid; e < CIN * KTAPS; e += 256) {
        const int ci = e / KTAPS;
        const float smod  = s0 * style_weight[ci * 2 + 0]
                          + s1 * style_weight[ci * 2 + 1]
                          + style_bias[ci];
        const float dsmod = style_weight[ci * 2 + 1];
        const float wt = weight[(co * CIN) * KTAPS + e];
        const float wv = wt * smod;
        const float dv = wt * dsmod;
        wsm[e]  = wv;
        dwsm[e] = dv;
        sw2 += wv * wv;
        swd += wv * dv;
    }
    red0[tid] = sw2;
    red1[tid] = swd;
    __syncthreads();
    for (int st = 128; st > 0; st >>= 1) {
        if (tid < st) { red0[tid] += red0[tid + st]; red1[tid] += red1[tid + st]; }
        __syncthreads();
    }
    const float norm  = sqrtf(red0[0] + EPS_);
    const float inv   = 1.0f / norm;
    const float dnorm = -red1[0] * inv * inv * inv;

    const size_t ob = (size_t)(b * COUT + co) * (CIN * KTAPS);
    for (int e = tid; e < CIN * KTAPS; e += 256) {
        g_wnv[ob + e] = wsm[e] * inv;
        g_dwv[ob + e] = dwsm[e] * inv + wsm[e] * dnorm;
    }
}

// ---------------------------------------------------------------------------
// Pack A tiles [k=ci 0..63][m=0..127], tf32-rounded.
//   kind 0 (B = x):  m<64 -> wn[co=m],  m>=64 -> dw[co=m-64]
//   kind 1 (B = dx): m<64 -> 0,         m>=64 -> wn[co=m-64]
// blk = (b*2 + kind)*27 + t
// ---------------------------------------------------------------------------
__global__ void pack_kernel()
{
    const int blk  = blockIdx.x;
    const int t    = blk % KTAPS;
    const int kind = (blk / KTAPS) & 1;
    const int b    = blk / (2 * KTAPS);
    float* dst = g_A + (size_t)blk * (64 * 128);

    for (int e = threadIdx.x; e < 64 * 128; e += 256) {
        const int k = e >> 7;      // ci
        const int m = e & 127;
        float v = 0.f;
        if (kind == 0) {
            v = (m < 64)
              ? g_wnv[(size_t)(b * COUT + m)        * (CIN * KTAPS) + k * KTAPS + t]
              : g_dwv[(size_t)(b * COUT + (m - 64)) * (CIN * KTAPS) + k * KTAPS + t];
        } else if (m >= 64) {
            v = g_wnv[(size_t)(b * COUT + (m - 64)) * (CIN * KTAPS) + k * KTAPS + t];
        }
        dst[e] = __uint_as_float(to_tf32(v));
    }
}

// ---------------------------------------------------------------------------
// Transpose NCDHW -> [b][z][y][x][c], tf32-rounded.
// ---------------------------------------------------------------------------
__global__ void transpose_kernel(const float* __restrict__ x, const float* __restrict__ dx)
{
    __shared__ float tile[64][65];
    const int tx = threadIdx.x;            // 0..31
    const int ty = threadIdx.y;            // 0..7
    const int y = blockIdx.x, z = blockIdx.y, b = blockIdx.z;

    const size_t in_base = (size_t)(b * 64) * 262144 + (size_t)z * 4096 + (size_t)y * 64;
    const size_t r0 = (((size_t)(b * 64 + z)) * 64 + y) * 64;

    const float* srcs[2] = { x, dx };
    float* dsts[2] = { g_xT, g_dxT };

    for (int pass = 0; pass < 2; pass++) {
        const float* src = srcs[pass];
        float* dst = dsts[pass];
        __syncthreads();
        for (int c = ty; c < 64; c += 8) {
            tile[c][tx]      = src[in_base + (size_t)c * 262144 + tx];
            tile[c][tx + 32] = src[in_base + (size_t)c * 262144 + tx + 32];
        }
        __syncthreads();
        for (int xr = ty; xr < 64; xr += 8) {
            dst[(r0 + xr) * 64 + tx]      = __uint_as_float(to_tf32(tile[tx][xr]));
            dst[(r0 + xr) * 64 + tx + 32] = __uint_as_float(to_tf32(tile[tx + 32][xr]));
        }
    }
}

// ---------------------------------------------------------------------------
// Conv implicit-GEMM with warp-level mma.sync (tf32).
// Grid (16 ytiles, 62 z, 2 b); block 512 threads = 16 warps (4M x 4N).
// D[m=128][n=256]: m 0..63 -> y couts, m 64..127 -> dy couts;
//                  n = (yy = n>>6)*64 + x.
// 2-stage cp.async pipeline; chunk c: kind = c>=27 (x vs dx), tap t = c%27.
// ---------------------------------------------------------------------------
__global__ __launch_bounds__(512, 1) void conv_mma_kernel(
    const float* __restrict__ bias, float* __restrict__ out)
{
    extern __shared__ __align__(16) float smem[];
    const uint32_t sb = smem_u32(smem);

    const int tid = threadIdx.x;
    const int wid = tid >> 5;
    const int lid = tid & 31;
    const int wm  = wid >> 2;          // M tile 0..3 (rows wm*32..)
    const int wn  = wid & 3;           // N tile 0..3 (cols wn*64..)
    const int g   = lid >> 2;          // group id 0..7
    const int ct  = lid & 3;           // thread-in-group

    const int y0 = blockIdx.x * 4;
    const int z0 = blockIdx.y;
    const int b  = blockIdx.z;

    float acc[2][8][4];
    #pragma unroll
    for (int mi = 0; mi < 2; ++mi)
        #pragma unroll
        for (int ni = 0; ni < 8; ++ni)
            #pragma unroll
            for (int j = 0; j < 4; ++j) acc[mi][ni][j] = 0.f;

    // ---- staging helper (all 512 threads) ----
    auto stage = [&](int c, int s) {
        const int kind = (c >= KTAPS) ? 1 : 0;
        const int t    = c - kind * KTAPS;
        // A: 64 rows x 128 floats -> rows padded to ST_A
        const float4* srcA = (const float4*)(g_A + (size_t)((b * 2 + kind) * KTAPS + t) * (64 * 128));
        const uint32_t dA = sb + s * STAGE;
        #pragma unroll
        for (int it = 0; it < 4; ++it) {
            const int i = tid + it * 512;           // 0..2047
            cp_async16(dA + (i >> 5) * (ST_A * 4) + (i & 31) * 16, srcA + i);
        }
        // B: 256 n-rows x 64 channels -> rows padded to ST_B
        const float* srcT = kind ? g_dxT : g_xT;
        const int dz  = t / 9;
        const int dyy = (t % 9) / 3;
        const int dxx = t % 3;
        const int rb  = ((b * 64 + (z0 + dz)) * 64 + (y0 + dyy)) * 64 + dxx;
        const uint32_t dB = sb + s * STAGE + A_BYTES;
        #pragma unroll
        for (int it = 0; it < 8; ++it) {
            const int i  = tid + it * 512;          // 0..4095
            const int n  = i >> 4;
            const int k4 = i & 15;
            const int r  = rb + (n >> 6) * 64 + (n & 63);
            cp_async16(dB + n * (ST_B * 4) + k4 * 16,
                       srcT + (size_t)r * 64 + k4 * 4);
        }
    };

    // ---- prologue ----
    stage(0, 0);
    asm volatile("cp.async.commit_group;" ::: "memory");
    stage(1, 1);
    asm volatile("cp.async.commit_group;" ::: "memory");

    const int m_base = wm * 32;
    const int n_base = wn * 64;

    for (int c = 0; c < NCHUNK; ++c) {
        asm volatile("cp.async.wait_group 1;" ::: "memory");
        __syncthreads();

        const int s = c & 1;
        // dx-chunks have zero A rows 0..63: warps owning M tiles 0..1 skip
        const bool active = !(c >= KTAPS && wm < 2);
        if (active) {
            const uint32_t* As = (const uint32_t*)((const char*)smem + s * STAGE);
            const uint32_t* Bs = (const uint32_t*)((const char*)smem + s * STAGE + A_BYTES);
            #pragma unroll
            for (int ks = 0; ks < 8; ++ks) {
                uint32_t a[2][4];
                #pragma unroll
                for (int mi = 0; mi < 2; ++mi) {
                    const int m0 = m_base + mi * 16 + g;
                    a[mi][0] = As[(ks * 8 + ct)     * ST_A + m0];
                    a[mi][1] = As[(ks * 8 + ct)     * ST_A + m0 + 8];
                    a[mi][2] = As[(ks * 8 + ct + 4) * ST_A + m0];
                    a[mi][3] = As[(ks * 8 + ct + 4) * ST_A + m0 + 8];
                }
                uint32_t bf[8][2];
                #pragma unroll
                for (int ni = 0; ni < 8; ++ni) {
                    const int n0 = n_base + ni * 8 + g;
                    bf[ni][0] = Bs[n0 * ST_B + ks * 8 + ct];
                    bf[ni][1] = Bs[n0 * ST_B + ks * 8 + ct + 4];
                }
                #pragma unroll
                for (int mi = 0; mi < 2; ++mi)
                    #pragma unroll
                    for (int ni = 0; ni < 8; ++ni)
                        mma_tf32(acc[mi][ni], a[mi], bf[ni]);
            }
        }
        __syncthreads();
        if (c + 2 < NCHUNK) stage(c + 2, s);
        asm volatile("cp.async.commit_group;" ::: "memory");
    }

    // ---- epilogue ----
    const size_t NOUT   = (size_t)DOUT * DOUT * DOUT;
    const size_t dy_off = (size_t)B_ * COUT * NOUT;

    #pragma unroll
    for (int mi = 0; mi < 2; ++mi) {
        #pragma unroll
        for (int h = 0; h < 2; ++h) {
            const int m  = m_base + mi * 16 + h * 8 + g;
            const bool isy = (m < 64);
            const int co = m & 63;
            const float bv = isy ? bias[co] : 0.f;
            const size_t outadd = isy ? 0 : dy_off;
            const size_t ob = ((size_t)(b * COUT + co) * DOUT + z0) * DOUT;
            #pragma unroll
            for (int ni = 0; ni < 8; ++ni) {
                const int n  = n_base + ni * 8 + ct * 2;
                const int yo = y0 + (n >> 6);
                const int xo = n & 63;
                if (yo < DOUT) {
                    const size_t idx = (ob + yo) * DOUT + xo;
                    if (xo < DOUT) {
                        out[outadd + idx]     = acc[mi][ni][h * 2 + 0] + bv;
                        out[outadd + idx + 1] = acc[mi][ni][h * 2 + 1] + bv;  // xo even => xo+1<62 when xo<62
                    }
                }
            }
        }
    }
}

// ---------------------------------------------------------------------------
// Launch. Inputs: x, s, dx, style_weight, style_bias, weight, bias.
// Output: concat(y, dy) fp32.
// ---------------------------------------------------------------------------
extern "C" void kernel_launch(void* const* d_in, const int* in_sizes, int n_in,
                              void* d_out, int out_size)
{
    const float* x    = (const float*)d_in[0];
    const float* s    = (const float*)d_in[1];
    const float* dx   = (const float*)d_in[2];
    const float* sw   = (const float*)d_in[3];
    const float* sb   = (const float*)d_in[4];
    const float* w    = (const float*)d_in[5];
    const float* bias = (const float*)d_in[6];
    float* out = (float*)d_out;

    cudaFuncSetAttribute(conv_mma_kernel, cudaFuncAttributeMaxDynamicSharedMemorySize, SMEM_DYN);

    prep_kernel<<<B_ * COUT, 256>>>(s, sw, sb, w);
    pack_kernel<<<B_ * 2 * KTAPS, 256>>>();
    transpose_kernel<<<dim3(64, 64, B_), dim3(32, 8)>>>(x, dx);
    conv_mma_kernel<<<dim3(16, 62, B_), 512, SMEM_DYN>>>(bias, out);
}

// round 5
// speedup vs baseline: 3.2797x; 1.0712x over previous
#include <cuda_runtime.h>
#include <cstdint>
#include <math.h>

// ---------------- problem constants ----------------
#define B_    2
#define CIN   64
#define COUT  64
#define DIN   64
#define DOUT  62
#define KTAPS 27
#define EPS_  1e-8f

#define NCHUNK 54                 // 27 taps x {x, dx}
#define ST_A   136                // floats per A smem row (k-major), 128 + 8 pad
#define ST_B   68                 // floats per B smem row (n-major), 64 + 4 pad
#define A_BYTES (64 * ST_A * 4)   // 34816
#define B_BYTES (256 * ST_B * 4)  // 69632
#define STAGE   (A_BYTES + B_BYTES)  // 104448
#define SMEM_DYN (2 * STAGE)         // 208896

// ---------------- device scratch ----------------
__device__ float g_wnv[B_ * COUT * CIN * KTAPS];
__device__ float g_dwv[B_ * COUT * CIN * KTAPS];
// A tiles: [b][kind][tap] x (64 k x 128 m) fp32(tf32-rounded), m contiguous
__device__ __align__(16) float g_A[B_ * 2 * KTAPS * 64 * 128];
// channel-last inputs [b][z][y][x][c], tf32-rounded, + pad for tap overreads
__device__ __align__(16) float g_xT [B_ * DIN * DIN * DIN * CIN + 16384];
__device__ __align__(16) float g_dxT[B_ * DIN * DIN * DIN * CIN + 16384];

// ---------------- helpers ----------------
__device__ __forceinline__ uint32_t smem_u32(const void* p) {
    uint32_t a;
    asm("{ .reg .u64 t; cvta.to.shared.u64 t, %1; cvt.u32.u64 %0, t; }" : "=r"(a) : "l"(p));
    return a;
}
__device__ __forceinline__ void cp_async16(uint32_t dst, const void* src) {
    asm volatile("cp.async.cg.shared.global [%0], [%1], 16;" :: "r"(dst), "l"(src) : "memory");
}
__device__ __forceinline__ uint32_t to_tf32(float v) {
    uint32_t u; asm("cvt.rna.tf32.f32 %0, %1;" : "=r"(u) : "f"(v)); return u;
}
__device__ __forceinline__ void mma_tf32(float* d, const uint32_t* a, const uint32_t* bfrag) {
    asm volatile(
        "mma.sync.aligned.m16n8k8.row.col.f32.tf32.tf32.f32 "
        "{%0,%1,%2,%3}, {%4,%5,%6,%7}, {%8,%9}, {%0,%1,%2,%3};"
        : "+f"(d[0]), "+f"(d[1]), "+f"(d[2]), "+f"(d[3])
        : "r"(a[0]), "r"(a[1]), "r"(a[2]), "r"(a[3]), "r"(bfrag[0]), "r"(bfrag[1]));
}

// ---------------------------------------------------------------------------
// Prep: style modulation + demodulation (validated round 2)
// output layout [b][co][ci*27+t]
// ---------------------------------------------------------------------------
__global__ void prep_kernel(const float* __restrict__ s,
                            const float* __restrict__ style_weight,
                            const float* __restrict__ style_bias,
                            const float* __restrict__ weight)
{
    __shared__ float wsm[CIN * KTAPS];
    __shared__ float dwsm[CIN * KTAPS];
    __shared__ float red0[256];
    __shared__ float red1[256];

    const int b  = blockIdx.x >> 6;
    const int co = blockIdx.x & 63;
    const int tid = threadIdx.x;

    const float s0 = s[b * 2 + 0];
    const float s1 = s[b * 2 + 1];

    float sw2 = 0.f, swd = 0.f;
    for (int e = tid; e < CIN * KTAPS; e += 256) {
        const int ci = e / KTAPS;
        const float smod  = s0 * style_weight[ci * 2 + 0]
                          + s1 * style_weight[ci * 2 + 1]
                          + style_bias[ci];
        const float dsmod = style_weight[ci * 2 + 1];
        const float wt = weight[(co * CIN) * KTAPS + e];
        const float wv = wt * smod;
        const float dv = wt * dsmod;
        wsm[e]  = wv;
        dwsm[e] = dv;
        sw2 += wv * wv;
        swd += wv * dv;
    }
    red0[tid] = sw2;
    red1[tid] = swd;
    __syncthreads();
    for (int st = 128; st > 0; st >>= 1) {
        if (tid < st) { red0[tid] += red0[tid + st]; red1[tid] += red1[tid + st]; }
        __syncthreads();
    }
    const float norm  = sqrtf(red0[0] + EPS_);
    const float inv   = 1.0f / norm;
    const float dnorm = -red1[0] * inv * inv * inv;

    const size_t ob = (size_t)(b * COUT + co) * (CIN * KTAPS);
    for (int e = tid; e < CIN * KTAPS; e += 256) {
        g_wnv[ob + e] = wsm[e] * inv;
        g_dwv[ob + e] = dwsm[e] * inv + wsm[e] * dnorm;
    }
}

// ---------------------------------------------------------------------------
// Pack A tiles [k=ci 0..63][m=0..127], tf32-rounded.
//   kind 0 (B = x):  m<64 -> wn[co=m],  m>=64 -> dw[co=m-64]
//   kind 1 (B = dx): m<64 -> 0,         m>=64 -> wn[co=m-64]
// blk = (b*2 + kind)*27 + t
// ---------------------------------------------------------------------------
__global__ void pack_kernel()
{
    const int blk  = blockIdx.x;
    const int t    = blk % KTAPS;
    const int kind = (blk / KTAPS) & 1;
    const int b    = blk / (2 * KTAPS);
    float* dst = g_A + (size_t)blk * (64 * 128);

    for (int e = threadIdx.x; e < 64 * 128; e += 256) {
        const int k = e >> 7;      // ci
        const int m = e & 127;
        float v = 0.f;
        if (kind == 0) {
            v = (m < 64)
              ? g_wnv[(size_t)(b * COUT + m)        * (CIN * KTAPS) + k * KTAPS + t]
              : g_dwv[(size_t)(b * COUT + (m - 64)) * (CIN * KTAPS) + k * KTAPS + t];
        } else if (m >= 64) {
            v = g_wnv[(size_t)(b * COUT + (m - 64)) * (CIN * KTAPS) + k * KTAPS + t];
        }
        dst[e] = __uint_as_float(to_tf32(v));
    }
}

// ---------------------------------------------------------------------------
// Transpose NCDHW -> [b][z][y][x][c], tf32-rounded.
// ---------------------------------------------------------------------------
__global__ void transpose_kernel(const float* __restrict__ x, const float* __restrict__ dx)
{
    __shared__ float tile[64][65];
    const int tx = threadIdx.x;            // 0..31
    const int ty = threadIdx.y;            // 0..7
    const int y = blockIdx.x, z = blockIdx.y, b = blockIdx.z;

    const size_t in_base = (size_t)(b * 64) * 262144 + (size_t)z * 4096 + (size_t)y * 64;
    const size_t r0 = (((size_t)(b * 64 + z)) * 64 + y) * 64;

    const float* srcs[2] = { x, dx };
    float* dsts[2] = { g_xT, g_dxT };

    for (int pass = 0; pass < 2; pass++) {
        const float* src = srcs[pass];
        float* dst = dsts[pass];
        __syncthreads();
        for (int c = ty; c < 64; c += 8) {
            tile[c][tx]      = src[in_base + (size_t)c * 262144 + tx];
            tile[c][tx + 32] = src[in_base + (size_t)c * 262144 + tx + 32];
        }
        __syncthreads();
        for (int xr = ty; xr < 64; xr += 8) {
            dst[(r0 + xr) * 64 + tx]      = __uint_as_float(to_tf32(tile[tx][xr]));
            dst[(r0 + xr) * 64 + tx + 32] = __uint_as_float(to_tf32(tile[tx + 32][xr]));
        }
    }
}

// ---------------------------------------------------------------------------
// Conv implicit-GEMM with warp-level mma.sync (tf32).
// Grid (16 ytiles, 62 z, 2 b); block 256 threads = 8 warps (2M x 4N),
// warp tile m64 x n64 (mi=4, ni=8)  ->  128 B smem per MMA (FLOP/byte = 16).
// D[m=128][n=256]: m 0..63 -> y couts, m 64..127 -> dy couts;
//                  n = (yy = n>>6)*64 + x.
// 2-stage cp.async pipeline; chunk c: kind = c>=27 (x vs dx), tap t = c%27.
// ---------------------------------------------------------------------------
__global__ __launch_bounds__(256, 1) void conv_mma_kernel(
    const float* __restrict__ bias, float* __restrict__ out)
{
    extern __shared__ __align__(16) float smem[];
    const uint32_t sb = smem_u32(smem);

    const int tid = threadIdx.x;
    const int wid = tid >> 5;
    const int lid = tid & 31;
    const int wm  = wid >> 2;          // M tile 0..1 (rows wm*64..)
    const int wn  = wid & 3;           // N tile 0..3 (cols wn*64..)
    const int g   = lid >> 2;          // group id 0..7
    const int ct  = lid & 3;           // thread-in-group

    const int y0 = blockIdx.x * 4;
    const int z0 = blockIdx.y;
    const int b  = blockIdx.z;

    float acc[4][8][4];
    #pragma unroll
    for (int mi = 0; mi < 4; ++mi)
        #pragma unroll
        for (int ni = 0; ni < 8; ++ni)
            #pragma unroll
            for (int j = 0; j < 4; ++j) acc[mi][ni][j] = 0.f;

    // ---- staging helper (all 256 threads) ----
    auto stage = [&](int c, int s) {
        const int kind = (c >= KTAPS) ? 1 : 0;
        const int t    = c - kind * KTAPS;
        // A: 64 rows x 128 floats -> rows padded to ST_A
        const float4* srcA = (const float4*)(g_A + (size_t)((b * 2 + kind) * KTAPS + t) * (64 * 128));
        const uint32_t dA = sb + s * STAGE;
        #pragma unroll
        for (int it = 0; it < 8; ++it) {
            const int i = tid + it * 256;           // 0..2047
            cp_async16(dA + (i >> 5) * (ST_A * 4) + (i & 31) * 16, srcA + i);
        }
        // B: 256 n-rows x 64 channels -> rows padded to ST_B
        const float* srcT = kind ? g_dxT : g_xT;
        const int dz  = t / 9;
        const int dyy = (t % 9) / 3;
        const int dxx = t % 3;
        const int rb  = ((b * 64 + (z0 + dz)) * 64 + (y0 + dyy)) * 64 + dxx;
        const uint32_t dB = sb + s * STAGE + A_BYTES;
        #pragma unroll
        for (int it = 0; it < 16; ++it) {
            const int i  = tid + it * 256;          // 0..4095
            const int n  = i >> 4;
            const int k4 = i & 15;
            const int r  = rb + (n >> 6) * 64 + (n & 63);
            cp_async16(dB + n * (ST_B * 4) + k4 * 16,
                       srcT + (size_t)r * 64 + k4 * 4);
        }
    };

    // ---- prologue ----
    stage(0, 0);
    asm volatile("cp.async.commit_group;" ::: "memory");
    stage(1, 1);
    asm volatile("cp.async.commit_group;" ::: "memory");

    const int m_base = wm * 64;
    const int n_base = wn * 64;

    for (int c = 0; c < NCHUNK; ++c) {
        asm volatile("cp.async.wait_group 1;" ::: "memory");
        __syncthreads();

        const int s = c & 1;
        // dx-chunks have zero A rows 0..63: warps owning M tile 0 skip
        const bool active = !(c >= KTAPS && wm == 0);
        if (active) {
            const uint32_t* As = (const uint32_t*)((const char*)smem + s * STAGE);
            const uint32_t* Bs = (const uint32_t*)((const char*)smem + s * STAGE + A_BYTES);
            #pragma unroll
            for (int ks = 0; ks < 8; ++ks) {
                uint32_t a[4][4];
                #pragma unroll
                for (int mi = 0; mi < 4; ++mi) {
                    const int m0 = m_base + mi * 16 + g;
                    a[mi][0] = As[(ks * 8 + ct)     * ST_A + m0];
                    a[mi][1] = As[(ks * 8 + ct)     * ST_A + m0 + 8];
                    a[mi][2] = As[(ks * 8 + ct + 4) * ST_A + m0];
                    a[mi][3] = As[(ks * 8 + ct + 4) * ST_A + m0 + 8];
                }
                uint32_t bf[8][2];
                #pragma unroll
                for (int ni = 0; ni < 8; ++ni) {
                    const int n0 = n_base + ni * 8 + g;
                    bf[ni][0] = Bs[n0 * ST_B + ks * 8 + ct];
                    bf[ni][1] = Bs[n0 * ST_B + ks * 8 + ct + 4];
                }
                #pragma unroll
                for (int mi = 0; mi < 4; ++mi)
                    #pragma unroll
                    for (int ni = 0; ni < 8; ++ni)
                        mma_tf32(acc[mi][ni], a[mi], bf[ni]);
            }
        }
        __syncthreads();
        if (c + 2 < NCHUNK) stage(c + 2, s);
        asm volatile("cp.async.commit_group;" ::: "memory");
    }

    // ---- epilogue ----
    const size_t NOUT   = (size_t)DOUT * DOUT * DOUT;
    const size_t dy_off = (size_t)B_ * COUT * NOUT;

    #pragma unroll
    for (int mi = 0; mi < 4; ++mi) {
        #pragma unroll
        for (int h = 0; h < 2; ++h) {
            const int m  = m_base + mi * 16 + h * 8 + g;
            const bool isy = (m < 64);
            const int co = m & 63;
            const float bv = isy ? bias[co] : 0.f;
            const size_t outadd = isy ? 0 : dy_off;
            const size_t ob = ((size_t)(b * COUT + co) * DOUT + z0) * DOUT;
            #pragma unroll
            for (int ni = 0; ni < 8; ++ni) {
                const int n  = n_base + ni * 8 + ct * 2;
                const int yo = y0 + (n >> 6);
                const int xo = n & 63;
                if (yo < DOUT) {
                    const size_t idx = (ob + yo) * DOUT + xo;
                    if (xo < DOUT) {
                        out[outadd + idx]     = acc[mi][ni][h * 2 + 0] + bv;
                        out[outadd + idx + 1] = acc[mi][ni][h * 2 + 1] + bv;  // xo even => xo+1 valid
                    }
                }
            }
        }
    }
}

// ---------------------------------------------------------------------------
// Launch. Inputs: x, s, dx, style_weight, style_bias, weight, bias.
// Output: concat(y, dy) fp32.
// ---------------------------------------------------------------------------
extern "C" void kernel_launch(void* const* d_in, const int* in_sizes, int n_in,
                              void* d_out, int out_size)
{
    const float* x    = (const float*)d_in[0];
    const float* s    = (const float*)d_in[1];
    const float* dx   = (const float*)d_in[2];
    const float* sw   = (const float*)d_in[3];
    const float* sb   = (const float*)d_in[4];
    const float* w    = (const float*)d_in[5];
    const float* bias = (const float*)d_in[6];
    float* out = (float*)d_out;

    cudaFuncSetAttribute(conv_mma_kernel, cudaFuncAttributeMaxDynamicSharedMemorySize, SMEM_DYN);

    prep_kernel<<<B_ * COUT, 256>>>(s, sw, sb, w);
    pack_kernel<<<B_ * 2 * KTAPS, 256>>>();
    transpose_kernel<<<dim3(64, 64, B_), dim3(32, 8)>>>(x, dx);
    conv_mma_kernel<<<dim3(16, 62, B_), 256, SMEM_DYN>>>(bias, out);
}